// round 8
// baseline (speedup 1.0000x reference)
#include <cuda_runtime.h>
#include <cuda_bf16.h>

#define NLAT 46
#define NLON 90
#define CH   256
#define SPX  (NLAT * NLON)   // 4140 spatial points

#define MAXNNZ 4096

// Scratch
__device__ float g_qc[CH * SPX];       // q channel-major [c][s]
__device__ float g_kc[CH * SPX];       // k channel-major [c][s]
__device__ float g_v [SPX * CH];       // v spatial-major [s][c]
__device__ float g_s [MAXNNZ * NLON];  // scores S[n][wo]
__device__ int   g_off[NLAT + 1];

// ---------------------------------------------------------------------------
// Fused projection GEMM (q, k, v by blockIdx.z):
//   out = W @ X + b ;  X: [CH][SPX], W: [CH][CH] row-major.
// BM=64 x BN=64 x BK=16, 64 threads, 8x8 micro-tile (plain FFMA).
// q,k stored channel-major [c][s]; v spatial-major [s][c].
// Block (0,0,0) also computes segment offsets.
// ---------------------------------------------------------------------------
__global__ void __launch_bounds__(64) proj_kernel(
    const float* __restrict__ qo, const float* __restrict__ ki,
    const float* __restrict__ vi,
    const float* __restrict__ q_w, const float* __restrict__ k_w,
    const float* __restrict__ v_w,
    const float* __restrict__ q_b, const float* __restrict__ k_b,
    const float* __restrict__ v_b,
    const int* __restrict__ row_ids, int nnz)
{
    const int which = blockIdx.z;
    const float* X    = (which == 0) ? qo  : (which == 1) ? ki  : vi;
    const float* W    = (which == 0) ? q_w : (which == 1) ? k_w : v_w;
    const float* bias = (which == 0) ? q_b : (which == 1) ? k_b : v_b;
    float* out        = (which == 0) ? g_qc : (which == 1) ? g_kc : g_v;

    const int tid = threadIdx.x;

    if (which == 0 && blockIdx.x == 0 && blockIdx.y == 0 && tid <= NLAT) {
        int lo = 0, hi = nnz;
        while (lo < hi) {
            int mid = (lo + hi) >> 1;
            if (row_ids[mid] < tid) lo = mid + 1; else hi = mid;
        }
        g_off[tid] = lo;
    }

    __shared__ __align__(16) float Xs[16][64];
    __shared__ __align__(16) float Ws[16][68];

    const int s0 = blockIdx.x * 64;
    const int n0 = blockIdx.y * 64;

    const int tm = (tid >> 3) * 4;   // 0..28
    const int tn = (tid & 7) * 4;    // 0..28

    float acc[8][8] = {};

    for (int c0 = 0; c0 < CH; c0 += 16) {
        #pragma unroll
        for (int r = 0; r < 4; ++r) {
            int idx = r * 64 + tid;
            int kk = idx >> 4, sm4 = idx & 15;
            int s = s0 + sm4 * 4;
            float4 xv = make_float4(0.f, 0.f, 0.f, 0.f);
            if (s < SPX)
                xv = *(const float4*)&X[(c0 + kk) * SPX + s];
            *(float4*)&Xs[kk][sm4 * 4] = xv;
        }
        #pragma unroll
        for (int r = 0; r < 4; ++r) {
            int idx = r * 64 + tid;
            int kn = idx >> 2, kk4 = (idx & 3) * 4;
            float4 wv = *(const float4*)&W[(n0 + kn) * CH + c0 + kk4];
            Ws[kk4 + 0][kn] = wv.x;
            Ws[kk4 + 1][kn] = wv.y;
            Ws[kk4 + 2][kn] = wv.z;
            Ws[kk4 + 3][kn] = wv.w;
        }
        __syncthreads();

        #pragma unroll
        for (int kk = 0; kk < 16; ++kk) {
            float4 a0 = *(const float4*)&Xs[kk][tm];
            float4 a1 = *(const float4*)&Xs[kk][tm + 32];
            float4 w0 = *(const float4*)&Ws[kk][tn];
            float4 w1 = *(const float4*)&Ws[kk][tn + 32];
            float av[8] = {a0.x, a0.y, a0.z, a0.w, a1.x, a1.y, a1.z, a1.w};
            float wv[8] = {w0.x, w0.y, w0.z, w0.w, w1.x, w1.y, w1.z, w1.w};
            #pragma unroll
            for (int i = 0; i < 8; ++i)
                #pragma unroll
                for (int j = 0; j < 8; ++j)
                    acc[i][j] += av[i] * wv[j];
        }
        __syncthreads();
    }

    float bv[8];
    #pragma unroll
    for (int j = 0; j < 4; ++j) {
        bv[j]     = __ldg(&bias[n0 + tn + j]);
        bv[j + 4] = __ldg(&bias[n0 + tn + 32 + j]);
    }

    if (which == 2) {
        // v: spatial-major [s][c]
        #pragma unroll
        for (int i = 0; i < 8; ++i) {
            int s = s0 + ((i < 4) ? (tm + i) : (tm + 32 + i - 4));
            if (s < SPX) {
                float4 o0, o1;
                o0.x = acc[i][0] + bv[0];  o0.y = acc[i][1] + bv[1];
                o0.z = acc[i][2] + bv[2];  o0.w = acc[i][3] + bv[3];
                o1.x = acc[i][4] + bv[4];  o1.y = acc[i][5] + bv[5];
                o1.z = acc[i][6] + bv[6];  o1.w = acc[i][7] + bv[7];
                *(float4*)&out[s * CH + n0 + tn]      = o0;
                *(float4*)&out[s * CH + n0 + tn + 32] = o1;
            }
        }
    } else {
        // q,k: channel-major [c][s]
        #pragma unroll
        for (int j = 0; j < 8; ++j) {
            int c = n0 + ((j < 4) ? (tn + j) : (tn + 28 + j));
            float b = bv[j];
            float4 lo, hi;
            lo.x = acc[0][j] + b; lo.y = acc[1][j] + b;
            lo.z = acc[2][j] + b; lo.w = acc[3][j] + b;
            hi.x = acc[4][j] + b; hi.y = acc[5][j] + b;
            hi.z = acc[6][j] + b; hi.w = acc[7][j] + b;
            if (s0 + tm < SPX)      *(float4*)&out[c * SPX + s0 + tm]      = lo;
            if (s0 + tm + 32 < SPX) *(float4*)&out[c * SPX + s0 + tm + 32] = hi;
        }
    }
}

// ---------------------------------------------------------------------------
// Score pass v2: S[n][wo] = exp(q[t,wo] . k[hi,(wi0+wo)%90]) * quad[hi]
// Grid: (t, neighbor-chunk-of-16, wo-block-of-32).  512 threads.
// q[256][32] staged in smem once per CTA; warp w handles neighbor beg+w.
// ---------------------------------------------------------------------------
__global__ void __launch_bounds__(512) score_kernel(
    const int*   __restrict__ col_idx,
    const float* __restrict__ quad)
{
    const int t = blockIdx.x;
    const int segbeg = g_off[t];
    const int segend = g_off[t + 1];
    const int beg = segbeg + blockIdx.y * 16;
    if (beg >= segend) return;                  // uniform early exit

    __shared__ float qs[CH][32];                // 32 KB

    const int tid = threadIdx.x;
    const int wo0 = blockIdx.z * 32;

    for (int i = tid; i < CH * 32; i += 512) {
        int c = i >> 5, j = i & 31;
        int wo = wo0 + j;
        qs[c][j] = (wo < NLON) ? g_qc[c * SPX + t * NLON + wo] : 0.0f;
    }
    __syncthreads();

    const int warp = tid >> 5;
    const int lane = tid & 31;
    const int n = beg + warp;
    if (n >= segend) return;

    const int ci  = __ldg(&col_idx[n]);
    const int hi  = ci / NLON;
    const int wi0 = ci - hi * NLON;

    const int wo   = wo0 + lane;
    const bool act = (wo < NLON);
    int wi = wi0 + (act ? wo : (NLON - 1));
    if (wi >= NLON) wi -= NLON;

    const float* kp = g_kc + hi * NLON + wi;

    float p0 = 0.f, p1 = 0.f, p2 = 0.f, p3 = 0.f;
    #pragma unroll 4
    for (int c = 0; c < CH; c += 4) {
        p0 += qs[c + 0][lane] * kp[(c + 0) * SPX];
        p1 += qs[c + 1][lane] * kp[(c + 1) * SPX];
        p2 += qs[c + 2][lane] * kp[(c + 2) * SPX];
        p3 += qs[c + 3][lane] * kp[(c + 3) * SPX];
    }
    float e = __expf((p0 + p1) + (p2 + p3)) * __ldg(&quad[hi]);
    if (act) g_s[n * NLON + wo] = e;
}

// ---------------------------------------------------------------------------
// Output pass v2: out[c][t][wo] = sum_n S[n][wo] * v[hi_n][(wi0_n+wo)%90][c] / d
// Grid: (t, 32-channel tile).  512 threads, warp = wo residue mod 16,
// lanes = channels.  v rows for hi in {t-1,t,t+1} staged in smem.
// ---------------------------------------------------------------------------
__global__ void __launch_bounds__(512) attn_out_kernel(
    const int* __restrict__ col_idx,
    float*     __restrict__ out)
{
    const int t  = blockIdx.x;
    const int c0 = blockIdx.y * 32;

    __shared__ float vs[3][NLON][32];   // 34.56 KB
    __shared__ float ds[NLON];
    __shared__ float ob[32][NLON + 1];  // padded: conflict-free transpose

    const int rlo = (t == 0) ? 0 : t - 1;
    const int rhi = (t == NLAT - 1) ? NLAT - 1 : t + 1;
    const int nrows = rhi - rlo + 1;

    const int tid = threadIdx.x;
    const int beg = g_off[t];
    const int end = g_off[t + 1];

    // Stage v rows (lanes -> consecutive channels: coalesced)
    for (int i = tid; i < nrows * NLON * 32; i += 512) {
        int r = i / (NLON * 32);
        int rem = i - r * (NLON * 32);
        int w = rem >> 5, c = rem & 31;
        vs[r][w][c] = g_v[((rlo + r) * NLON + w) * CH + c0 + c];
    }
    // Denominators
    if (tid < NLON) {
        float d = 0.0f;
        for (int n = beg; n < end; ++n)
            d += g_s[n * NLON + tid];
        ds[tid] = d;
    }
    __syncthreads();

    const int warp = tid >> 5;      // 0..15 = wo residue
    const int lane = tid & 31;      // channel

    float acc[6] = {0.f, 0.f, 0.f, 0.f, 0.f, 0.f};

    for (int n = beg; n < end; ++n) {
        int ci  = __ldg(&col_idx[n]);
        int r   = ci / NLON;
        int wi0 = ci - r * NLON;
        r -= rlo;
        const float* srow = g_s + n * NLON;
        #pragma unroll
        for (int k = 0; k < 6; ++k) {
            int wo = warp + 16 * k;
            if (wo < NLON) {
                float e = __ldg(&srow[wo]);       // uniform broadcast
                int wi = wi0 + wo;
                if (wi >= NLON) wi -= NLON;
                acc[k] += e * vs[r][wi][lane];    // conflict-free LDS
            }
        }
    }

    #pragma unroll
    for (int k = 0; k < 6; ++k) {
        int wo = warp + 16 * k;
        if (wo < NLON)
            ob[lane][wo] = acc[k] / ds[wo];
    }
    __syncthreads();

    // Coalesced store: rows of 90 consecutive positions per channel.
    const int base = t * NLON;
    for (int i = tid; i < 32 * NLON; i += 512) {
        int c = i / NLON, w = i - c * NLON;
        out[(c0 + c) * SPX + base + w] = ob[c][w];
    }
}

// ---------------------------------------------------------------------------
extern "C" void kernel_launch(void* const* d_in, const int* in_sizes, int n_in,
                              void* d_out, int out_size)
{
    const float* qo   = (const float*)d_in[0];
    const float* ki   = (const float*)d_in[1];
    const float* vi   = (const float*)d_in[2];
    const float* q_w  = (const float*)d_in[3];
    const float* k_w  = (const float*)d_in[4];
    const float* v_w  = (const float*)d_in[5];
    const float* q_b  = (const float*)d_in[6];
    const float* k_b  = (const float*)d_in[7];
    const float* v_b  = (const float*)d_in[8];
    const float* quad = (const float*)d_in[9];
    const int* row_ids = (const int*)d_in[10];
    const int* col_idx = (const int*)d_in[11];
    const int nnz = in_sizes[10];

    float* out = (float*)d_out;

    dim3 gg((SPX + 63) / 64, CH / 64, 3);
    proj_kernel<<<gg, 64>>>(qo, ki, vi, q_w, k_w, v_w, q_b, k_b, v_b,
                            row_ids, nnz);

    // 16 chunks x 16 neighbors = 256 >= max segment (~180); extras early-exit.
    score_kernel<<<dim3(NLAT, 16, 3), 512>>>(col_idx, quad);

    attn_out_kernel<<<dim3(NLAT, CH / 32), 512>>>(col_idx, out);
}

// round 10
// speedup vs baseline: 1.0300x; 1.0300x over previous
#include <cuda_runtime.h>
#include <cuda_bf16.h>

#define NLAT 46
#define NLON 90
#define CH   256
#define SPX  (NLAT * NLON)   // 4140 spatial points

// Heavy rows: 0, 1, 44, 45 (pole rows + rows containing a full pole circle)
#define HEAVY_BLOCKS (4 * NLON)                 // 360: one CTA per heavy point
#define LIGHT_BEG    (2 * NLON)                 // pos 180  (row 2)
#define LIGHT_END    (44 * NLON)                // pos 3960 (end of row 43)
#define LIGHT_BLOCKS ((LIGHT_END - LIGHT_BEG + 7) / 8)   // 473

#define MAXNNZ 4096

// Scratch
__device__ float g_qc[CH * SPX];       // q channel-major [c][s]
__device__ float g_kc[CH * SPX];       // k channel-major [c][s]
__device__ float g_v [SPX * CH];       // v spatial-major [s][c]
__device__ float g_s [MAXNNZ * NLON];  // scores S[n][wo]
__device__ int   g_off[NLAT + 1];

// ---------------------------------------------------------------------------
// Fused projection GEMM (q, k, v by blockIdx.z):
//   out = W @ X + b ;  X: [CH][SPX], W: [CH][CH] row-major.
// BM=64 x BN=64 x BK=16, 64 threads, 8x8 micro-tile (plain FFMA — measured at
// the FFMA roofline, 44.6us).  q,k stored channel-major; v spatial-major.
// Block (0,0,0) also computes segment offsets.
// ---------------------------------------------------------------------------
__global__ void __launch_bounds__(64) proj_kernel(
    const float* __restrict__ qo, const float* __restrict__ ki,
    const float* __restrict__ vi,
    const float* __restrict__ q_w, const float* __restrict__ k_w,
    const float* __restrict__ v_w,
    const float* __restrict__ q_b, const float* __restrict__ k_b,
    const float* __restrict__ v_b,
    const int* __restrict__ row_ids, int nnz)
{
    const int which = blockIdx.z;
    const float* X    = (which == 0) ? qo  : (which == 1) ? ki  : vi;
    const float* W    = (which == 0) ? q_w : (which == 1) ? k_w : v_w;
    const float* bias = (which == 0) ? q_b : (which == 1) ? k_b : v_b;
    float* out        = (which == 0) ? g_qc : (which == 1) ? g_kc : g_v;

    const int tid = threadIdx.x;

    if (which == 0 && blockIdx.x == 0 && blockIdx.y == 0 && tid <= NLAT) {
        int lo = 0, hi = nnz;
        while (lo < hi) {
            int mid = (lo + hi) >> 1;
            if (row_ids[mid] < tid) lo = mid + 1; else hi = mid;
        }
        g_off[tid] = lo;
    }

    __shared__ __align__(16) float Xs[16][64];
    __shared__ __align__(16) float Ws[16][68];

    const int s0 = blockIdx.x * 64;
    const int n0 = blockIdx.y * 64;

    const int tm = (tid >> 3) * 4;   // 0..28
    const int tn = (tid & 7) * 4;    // 0..28

    float acc[8][8] = {};

    for (int c0 = 0; c0 < CH; c0 += 16) {
        #pragma unroll
        for (int r = 0; r < 4; ++r) {
            int idx = r * 64 + tid;
            int kk = idx >> 4, sm4 = idx & 15;
            int s = s0 + sm4 * 4;
            float4 xv = make_float4(0.f, 0.f, 0.f, 0.f);
            if (s < SPX)
                xv = *(const float4*)&X[(c0 + kk) * SPX + s];
            *(float4*)&Xs[kk][sm4 * 4] = xv;
        }
        #pragma unroll
        for (int r = 0; r < 4; ++r) {
            int idx = r * 64 + tid;
            int kn = idx >> 2, kk4 = (idx & 3) * 4;
            float4 wv = *(const float4*)&W[(n0 + kn) * CH + c0 + kk4];
            Ws[kk4 + 0][kn] = wv.x;
            Ws[kk4 + 1][kn] = wv.y;
            Ws[kk4 + 2][kn] = wv.z;
            Ws[kk4 + 3][kn] = wv.w;
        }
        __syncthreads();

        #pragma unroll
        for (int kk = 0; kk < 16; ++kk) {
            float4 a0 = *(const float4*)&Xs[kk][tm];
            float4 a1 = *(const float4*)&Xs[kk][tm + 32];
            float4 w0 = *(const float4*)&Ws[kk][tn];
            float4 w1 = *(const float4*)&Ws[kk][tn + 32];
            float av[8] = {a0.x, a0.y, a0.z, a0.w, a1.x, a1.y, a1.z, a1.w};
            float wv[8] = {w0.x, w0.y, w0.z, w0.w, w1.x, w1.y, w1.z, w1.w};
            #pragma unroll
            for (int i = 0; i < 8; ++i)
                #pragma unroll
                for (int j = 0; j < 8; ++j)
                    acc[i][j] += av[i] * wv[j];
        }
        __syncthreads();
    }

    float bv[8];
    #pragma unroll
    for (int j = 0; j < 4; ++j) {
        bv[j]     = __ldg(&bias[n0 + tn + j]);
        bv[j + 4] = __ldg(&bias[n0 + tn + 32 + j]);
    }

    if (which == 2) {
        #pragma unroll
        for (int i = 0; i < 8; ++i) {
            int s = s0 + ((i < 4) ? (tm + i) : (tm + 32 + i - 4));
            if (s < SPX) {
                float4 o0, o1;
                o0.x = acc[i][0] + bv[0];  o0.y = acc[i][1] + bv[1];
                o0.z = acc[i][2] + bv[2];  o0.w = acc[i][3] + bv[3];
                o1.x = acc[i][4] + bv[4];  o1.y = acc[i][5] + bv[5];
                o1.z = acc[i][6] + bv[6];  o1.w = acc[i][7] + bv[7];
                *(float4*)&out[s * CH + n0 + tn]      = o0;
                *(float4*)&out[s * CH + n0 + tn + 32] = o1;
            }
        }
    } else {
        #pragma unroll
        for (int j = 0; j < 8; ++j) {
            int c = n0 + ((j < 4) ? (tn + j) : (tn + 28 + j));
            float b = bv[j];
            float4 lo, hi;
            lo.x = acc[0][j] + b; lo.y = acc[1][j] + b;
            lo.z = acc[2][j] + b; lo.w = acc[3][j] + b;
            hi.x = acc[4][j] + b; hi.y = acc[5][j] + b;
            hi.z = acc[6][j] + b; hi.w = acc[7][j] + b;
            if (s0 + tm < SPX)      *(float4*)&out[c * SPX + s0 + tm]      = lo;
            if (s0 + tm + 32 < SPX) *(float4*)&out[c * SPX + s0 + tm + 32] = hi;
        }
    }
}

// ---------------------------------------------------------------------------
// Score pass v3: S[n][wo] = exp(q[t,wo] . k[hi,(wi0+wo)%90]) * quad[hi]
// One warp per (4-neighbor chunk, 32-wide wo block); lanes span wo.
// q column loaded ONCE per warp and shared across the 4 neighbors
// (1 q-LDG + 4 k-LDG + 4 FMA per channel step -> ~37% less traffic than
// warp-per-neighbor, with 4 independent FMA chains).
// Grid: (t, chunk-block, wo-block of 32).  256 threads = 8 chunks/CTA.
// ---------------------------------------------------------------------------
__global__ void __launch_bounds__(256) score_kernel(
    const int*   __restrict__ col_idx,
    const float* __restrict__ quad)
{
    const int t   = blockIdx.x;
    const int beg = g_off[t];
    const int end = g_off[t + 1];

    const int warp  = threadIdx.x >> 5;
    const int lane  = threadIdx.x & 31;
    const int chunk = blockIdx.y * 8 + warp;      // 0..47
    const int n0    = beg + chunk * 4;
    if (n0 >= end) return;
    const int cnt = min(4, end - n0);

    const int wo   = blockIdx.z * 32 + lane;
    const bool act = (wo < NLON);
    const int woc  = act ? wo : (NLON - 1);

    int hia[4];
    const float* kp[4];
    #pragma unroll
    for (int j = 0; j < 4; ++j) {
        int jj = (j < cnt) ? j : (cnt - 1);
        int ci = __ldg(&col_idx[n0 + jj]);
        int hi = ci / NLON;
        int wi = ci - hi * NLON + woc;
        if (wi >= NLON) wi -= NLON;
        hia[j] = hi;
        kp[j] = g_kc + hi * NLON + wi;
    }

    const float* qp = g_qc + t * NLON + woc;

    float p0 = 0.f, p1 = 0.f, p2 = 0.f, p3 = 0.f;
    #pragma unroll 4
    for (int c = 0; c < CH; ++c) {
        float qv = qp[0];
        p0 += qv * kp[0][0];
        p1 += qv * kp[1][0];
        p2 += qv * kp[2][0];
        p3 += qv * kp[3][0];
        qp += SPX;
        kp[0] += SPX; kp[1] += SPX; kp[2] += SPX; kp[3] += SPX;
    }

    if (act) {
        float e0 = __expf(p0) * __ldg(&quad[hia[0]]);
        g_s[(n0 + 0) * NLON + wo] = e0;
        if (cnt > 1) g_s[(n0 + 1) * NLON + wo] = __expf(p1) * __ldg(&quad[hia[1]]);
        if (cnt > 2) g_s[(n0 + 2) * NLON + wo] = __expf(p2) * __ldg(&quad[hia[2]]);
        if (cnt > 3) g_s[(n0 + 3) * NLON + wo] = __expf(p3) * __ldg(&quad[hia[3]]);
    }
}

// ---------------------------------------------------------------------------
// Output pass (r7, measured-good): out[c][pos] = sum_n S[n][wo]*v[nbr][c] / d
// Heavy (rows 0,1,44,45): one CTA per point, 8 warps stride neighbors.
// Light (rows 2..43): warp per point, smem-transposed coalesced store.
// ---------------------------------------------------------------------------
__device__ __forceinline__ void out_step(
    int n, int wo, int lane,
    const int* __restrict__ col_idx,
    float& d, float4& a0, float4& a1)
{
    int ci = __ldg(&col_idx[n]);
    int hi = ci / NLON;
    int wi = ci - hi * NLON + wo;
    if (wi >= NLON) wi -= NLON;
    int base = (hi * NLON + wi) * CH;

    float e = __ldg(&g_s[n * NLON + wo]);

    const float4* vv = (const float4*)(g_v + base);
    float4 v0 = vv[lane];
    float4 v1 = vv[lane + 32];

    d += e;
    a0.x += e * v0.x;  a0.y += e * v0.y;
    a0.z += e * v0.z;  a0.w += e * v0.w;
    a1.x += e * v1.x;  a1.y += e * v1.y;
    a1.z += e * v1.z;  a1.w += e * v1.w;
}

__global__ void __launch_bounds__(256) attn_out_kernel(
    const int* __restrict__ col_idx,
    float*     __restrict__ out)
{
    __shared__ float smem[2304];   // heavy: [8][256]+[8] | light: [256][9]

    const int warp = threadIdx.x >> 5;
    const int lane = threadIdx.x & 31;

    if (blockIdx.x < HEAVY_BLOCKS) {
        const int bi = blockIdx.x;
        int r = bi / NLON;                             // 0..3
        const int t  = (r < 2) ? r : (NLAT - 4 + r);   // 0,1,44,45
        const int wo = bi - r * NLON;
        const int pos = t * NLON + wo;

        float d = 0.0f;
        float4 a0 = make_float4(0.f, 0.f, 0.f, 0.f);
        float4 a1 = make_float4(0.f, 0.f, 0.f, 0.f);

        const int beg = g_off[t];
        const int end = g_off[t + 1];

        #pragma unroll 2
        for (int n = beg + warp; n < end; n += 8)
            out_step(n, wo, lane, col_idx, d, a0, a1);

        float* sb = smem + warp * 256;
        *(float4*)&sb[lane * 4]       = a0;
        *(float4*)&sb[128 + lane * 4] = a1;
        if (lane == 0) smem[2048 + warp] = d;
        __syncthreads();

        const int c = threadIdx.x;
        float s = 0.0f, dt = 0.0f;
        #pragma unroll
        for (int w = 0; w < 8; ++w) s  += smem[w * 256 + c];
        #pragma unroll
        for (int w = 0; w < 8; ++w) dt += smem[2048 + w];
        out[c * SPX + pos] = s / dt;
    } else {
        const int pos0 = LIGHT_BEG + (blockIdx.x - HEAVY_BLOCKS) * 8;
        const int gw   = pos0 + warp;

        if (gw < LIGHT_END) {
            const int t  = gw / NLON;
            const int wo = gw - t * NLON;

            float d = 0.0f;
            float4 a0 = make_float4(0.f, 0.f, 0.f, 0.f);
            float4 a1 = make_float4(0.f, 0.f, 0.f, 0.f);

            const int beg = g_off[t];
            const int end = g_off[t + 1];

            #pragma unroll 2
            for (int n = beg; n < end; ++n)
                out_step(n, wo, lane, col_idx, d, a0, a1);

            const float inv = 1.0f / d;
            const int c0 = lane * 4;
            smem[(c0 + 0) * 9 + warp] = a0.x * inv;
            smem[(c0 + 1) * 9 + warp] = a0.y * inv;
            smem[(c0 + 2) * 9 + warp] = a0.z * inv;
            smem[(c0 + 3) * 9 + warp] = a0.w * inv;
            smem[(c0 + 128) * 9 + warp] = a1.x * inv;
            smem[(c0 + 129) * 9 + warp] = a1.y * inv;
            smem[(c0 + 130) * 9 + warp] = a1.z * inv;
            smem[(c0 + 131) * 9 + warp] = a1.w * inv;
        }
        __syncthreads();

        const int p  = threadIdx.x & 7;
        const int cb = threadIdx.x >> 3;
        if (pos0 + p < LIGHT_END) {
            #pragma unroll
            for (int j = 0; j < 8; ++j) {
                int c = cb + j * 32;
                out[c * SPX + pos0 + p] = smem[c * 9 + p];
            }
        }
    }
}

// ---------------------------------------------------------------------------
extern "C" void kernel_launch(void* const* d_in, const int* in_sizes, int n_in,
                              void* d_out, int out_size)
{
    const float* qo   = (const float*)d_in[0];
    const float* ki   = (const float*)d_in[1];
    const float* vi   = (const float*)d_in[2];
    const float* q_w  = (const float*)d_in[3];
    const float* k_w  = (const float*)d_in[4];
    const float* v_w  = (const float*)d_in[5];
    const float* q_b  = (const float*)d_in[6];
    const float* k_b  = (const float*)d_in[7];
    const float* v_b  = (const float*)d_in[8];
    const float* quad = (const float*)d_in[9];
    const int* row_ids = (const int*)d_in[10];
    const int* col_idx = (const int*)d_in[11];
    const int nnz = in_sizes[10];

    float* out = (float*)d_out;

    dim3 gg((SPX + 63) / 64, CH / 64, 3);
    proj_kernel<<<gg, 64>>>(qo, ki, vi, q_w, k_w, v_w, q_b, k_b, v_b,
                            row_ids, nnz);

    // 6 chunk-blocks x 8 warps x 4 nbrs = 192 >= max segment (~180)
    score_kernel<<<dim3(NLAT, 6, 3), 256>>>(col_idx, quad);

    attn_out_kernel<<<HEAVY_BLOCKS + LIGHT_BLOCKS, 256>>>(col_idx, out);
}

// round 11
// speedup vs baseline: 1.7502x; 1.6992x over previous
#include <cuda_runtime.h>
#include <cuda_bf16.h>

#define NLAT 46
#define NLON 90
#define CH   256
#define SPX  (NLAT * NLON)   // 4140 spatial points

// Heavy rows: 0, 1, 44, 45 (pole rows + rows containing a full pole circle)
#define HEAVY_BLOCKS (4 * NLON)                 // 360: one CTA per heavy point
#define LIGHT_BEG    (2 * NLON)                 // pos 180  (row 2)
#define LIGHT_END    (44 * NLON)                // pos 3960 (end of row 43)
#define LIGHT_BLOCKS ((LIGHT_END - LIGHT_BEG + 7) / 8)   // 473

#define MAXNNZ 4096

// Scratch
__device__ float g_qc[CH * SPX];       // q channel-major [c][s]
__device__ float g_kc[CH * SPX];       // k channel-major [c][s]
__device__ float g_v [SPX * CH];       // v spatial-major [s][c]
__device__ float g_s [MAXNNZ * NLON];  // scores S[n][wo]
__device__ int   g_off[NLAT + 1];

// ---------------------------------------------------------------------------
// Fused projection GEMM (q, k, v by blockIdx.z):
//   out = W @ X + b ;  X: [CH][SPX], W: [CH][CH] row-major.
// BM=64 x BN=64 x BK=16, 64 threads, 8x8 micro-tile (plain FFMA — measured at
// the FFMA roofline, ~45us).  q,k stored channel-major; v spatial-major.
// Block (0,0,0) also computes segment offsets.
// ---------------------------------------------------------------------------
__global__ void __launch_bounds__(64) proj_kernel(
    const float* __restrict__ qo, const float* __restrict__ ki,
    const float* __restrict__ vi,
    const float* __restrict__ q_w, const float* __restrict__ k_w,
    const float* __restrict__ v_w,
    const float* __restrict__ q_b, const float* __restrict__ k_b,
    const float* __restrict__ v_b,
    const int* __restrict__ row_ids, int nnz)
{
    const int which = blockIdx.z;
    const float* X    = (which == 0) ? qo  : (which == 1) ? ki  : vi;
    const float* W    = (which == 0) ? q_w : (which == 1) ? k_w : v_w;
    const float* bias = (which == 0) ? q_b : (which == 1) ? k_b : v_b;
    float* out        = (which == 0) ? g_qc : (which == 1) ? g_kc : g_v;

    const int tid = threadIdx.x;

    if (which == 0 && blockIdx.x == 0 && blockIdx.y == 0 && tid <= NLAT) {
        int lo = 0, hi = nnz;
        while (lo < hi) {
            int mid = (lo + hi) >> 1;
            if (row_ids[mid] < tid) lo = mid + 1; else hi = mid;
        }
        g_off[tid] = lo;
    }

    __shared__ __align__(16) float Xs[16][64];
    __shared__ __align__(16) float Ws[16][68];

    const int s0 = blockIdx.x * 64;
    const int n0 = blockIdx.y * 64;

    const int tm = (tid >> 3) * 4;   // 0..28
    const int tn = (tid & 7) * 4;    // 0..28

    float acc[8][8] = {};

    for (int c0 = 0; c0 < CH; c0 += 16) {
        #pragma unroll
        for (int r = 0; r < 4; ++r) {
            int idx = r * 64 + tid;
            int kk = idx >> 4, sm4 = idx & 15;
            int s = s0 + sm4 * 4;
            float4 xv = make_float4(0.f, 0.f, 0.f, 0.f);
            if (s < SPX)
                xv = *(const float4*)&X[(c0 + kk) * SPX + s];
            *(float4*)&Xs[kk][sm4 * 4] = xv;
        }
        #pragma unroll
        for (int r = 0; r < 4; ++r) {
            int idx = r * 64 + tid;
            int kn = idx >> 2, kk4 = (idx & 3) * 4;
            float4 wv = *(const float4*)&W[(n0 + kn) * CH + c0 + kk4];
            Ws[kk4 + 0][kn] = wv.x;
            Ws[kk4 + 1][kn] = wv.y;
            Ws[kk4 + 2][kn] = wv.z;
            Ws[kk4 + 3][kn] = wv.w;
        }
        __syncthreads();

        #pragma unroll
        for (int kk = 0; kk < 16; ++kk) {
            float4 a0 = *(const float4*)&Xs[kk][tm];
            float4 a1 = *(const float4*)&Xs[kk][tm + 32];
            float4 w0 = *(const float4*)&Ws[kk][tn];
            float4 w1 = *(const float4*)&Ws[kk][tn + 32];
            float av[8] = {a0.x, a0.y, a0.z, a0.w, a1.x, a1.y, a1.z, a1.w};
            float wv[8] = {w0.x, w0.y, w0.z, w0.w, w1.x, w1.y, w1.z, w1.w};
            #pragma unroll
            for (int i = 0; i < 8; ++i)
                #pragma unroll
                for (int j = 0; j < 8; ++j)
                    acc[i][j] += av[i] * wv[j];
        }
        __syncthreads();
    }

    float bv[8];
    #pragma unroll
    for (int j = 0; j < 4; ++j) {
        bv[j]     = __ldg(&bias[n0 + tn + j]);
        bv[j + 4] = __ldg(&bias[n0 + tn + 32 + j]);
    }

    if (which == 2) {
        #pragma unroll
        for (int i = 0; i < 8; ++i) {
            int s = s0 + ((i < 4) ? (tm + i) : (tm + 32 + i - 4));
            if (s < SPX) {
                float4 o0, o1;
                o0.x = acc[i][0] + bv[0];  o0.y = acc[i][1] + bv[1];
                o0.z = acc[i][2] + bv[2];  o0.w = acc[i][3] + bv[3];
                o1.x = acc[i][4] + bv[4];  o1.y = acc[i][5] + bv[5];
                o1.z = acc[i][6] + bv[6];  o1.w = acc[i][7] + bv[7];
                *(float4*)&out[s * CH + n0 + tn]      = o0;
                *(float4*)&out[s * CH + n0 + tn + 32] = o1;
            }
        }
    } else {
        #pragma unroll
        for (int j = 0; j < 8; ++j) {
            int c = n0 + ((j < 4) ? (tn + j) : (tn + 28 + j));
            float b = bv[j];
            float4 lo, hi;
            lo.x = acc[0][j] + b; lo.y = acc[1][j] + b;
            lo.z = acc[2][j] + b; lo.w = acc[3][j] + b;
            hi.x = acc[4][j] + b; hi.y = acc[5][j] + b;
            hi.z = acc[6][j] + b; hi.w = acc[7][j] + b;
            if (s0 + tm < SPX)      *(float4*)&out[c * SPX + s0 + tm]      = lo;
            if (s0 + tm + 32 < SPX) *(float4*)&out[c * SPX + s0 + tm + 32] = hi;
        }
    }
}

// ---------------------------------------------------------------------------
// Score pass (r7 exact — measured good):
//   S[n][wo] = exp(q[t_n,wo] . k[h_n,(w_n+wo)%NLON]) * quad[h_n]
// One warp per (neighbor n, 32-wide wo block). Lanes span wo -> coalesced.
// Thread-local 256-FMA dot with 4 independent chains: no shuffles, high MLP,
// ~5700 live warps (never trade warp count for per-warp reuse here).
// ---------------------------------------------------------------------------
__global__ void __launch_bounds__(256) score_kernel(
    const int*   __restrict__ row_ids,
    const int*   __restrict__ col_idx,
    const float* __restrict__ quad,
    int nnz)
{
    const int w    = (int)((blockIdx.x * 256 + threadIdx.x) >> 5);
    const int lane = threadIdx.x & 31;
    const int n    = w / 3;
    const int wb   = w - n * 3;
    if (n >= nnz) return;

    const int t   = __ldg(&row_ids[n]);
    const int ci  = __ldg(&col_idx[n]);
    const int hi  = ci / NLON;
    const int wi0 = ci - hi * NLON;

    const int wo  = wb * 32 + lane;
    const bool act = (wo < NLON);
    const int woc = act ? wo : 0;
    int wi = wi0 + woc;
    if (wi >= NLON) wi -= NLON;

    const float* qp = g_qc + t * NLON + woc;
    const float* kp = g_kc + hi * NLON + wi;

    float p0 = 0.f, p1 = 0.f, p2 = 0.f, p3 = 0.f;
    #pragma unroll 4
    for (int c = 0; c < CH; c += 4) {
        p0 += qp[0 * SPX] * kp[0 * SPX];
        p1 += qp[1 * SPX] * kp[1 * SPX];
        p2 += qp[2 * SPX] * kp[2 * SPX];
        p3 += qp[3 * SPX] * kp[3 * SPX];
        qp += 4 * SPX; kp += 4 * SPX;
    }
    float e = __expf((p0 + p1) + (p2 + p3)) * __ldg(&quad[hi]);
    if (act) g_s[n * NLON + wo] = e;
}

// ---------------------------------------------------------------------------
// Output pass (r7, measured-good): out[c][pos] = sum_n S[n][wo]*v[nbr][c] / d
// Heavy (rows 0,1,44,45): one CTA per point, 8 warps stride neighbors.
// Light (rows 2..43): warp per point, smem-transposed coalesced store.
// ---------------------------------------------------------------------------
__device__ __forceinline__ void out_step(
    int n, int wo, int lane,
    const int* __restrict__ col_idx,
    float& d, float4& a0, float4& a1)
{
    int ci = __ldg(&col_idx[n]);
    int hi = ci / NLON;
    int wi = ci - hi * NLON + wo;
    if (wi >= NLON) wi -= NLON;
    int base = (hi * NLON + wi) * CH;

    float e = __ldg(&g_s[n * NLON + wo]);

    const float4* vv = (const float4*)(g_v + base);
    float4 v0 = vv[lane];
    float4 v1 = vv[lane + 32];

    d += e;
    a0.x += e * v0.x;  a0.y += e * v0.y;
    a0.z += e * v0.z;  a0.w += e * v0.w;
    a1.x += e * v1.x;  a1.y += e * v1.y;
    a1.z += e * v1.z;  a1.w += e * v1.w;
}

__global__ void __launch_bounds__(256) attn_out_kernel(
    const int* __restrict__ col_idx,
    float*     __restrict__ out)
{
    __shared__ float smem[2304];   // heavy: [8][256]+[8] | light: [256][9]

    const int warp = threadIdx.x >> 5;
    const int lane = threadIdx.x & 31;

    if (blockIdx.x < HEAVY_BLOCKS) {
        const int bi = blockIdx.x;
        int r = bi / NLON;                             // 0..3
        const int t  = (r < 2) ? r : (NLAT - 4 + r);   // 0,1,44,45
        const int wo = bi - r * NLON;
        const int pos = t * NLON + wo;

        float d = 0.0f;
        float4 a0 = make_float4(0.f, 0.f, 0.f, 0.f);
        float4 a1 = make_float4(0.f, 0.f, 0.f, 0.f);

        const int beg = g_off[t];
        const int end = g_off[t + 1];

        #pragma unroll 2
        for (int n = beg + warp; n < end; n += 8)
            out_step(n, wo, lane, col_idx, d, a0, a1);

        float* sb = smem + warp * 256;
        *(float4*)&sb[lane * 4]       = a0;
        *(float4*)&sb[128 + lane * 4] = a1;
        if (lane == 0) smem[2048 + warp] = d;
        __syncthreads();

        const int c = threadIdx.x;
        float s = 0.0f, dt = 0.0f;
        #pragma unroll
        for (int w = 0; w < 8; ++w) s  += smem[w * 256 + c];
        #pragma unroll
        for (int w = 0; w < 8; ++w) dt += smem[2048 + w];
        out[c * SPX + pos] = s / dt;
    } else {
        const int pos0 = LIGHT_BEG + (blockIdx.x - HEAVY_BLOCKS) * 8;
        const int gw   = pos0 + warp;

        if (gw < LIGHT_END) {
            const int t  = gw / NLON;
            const int wo = gw - t * NLON;

            float d = 0.0f;
            float4 a0 = make_float4(0.f, 0.f, 0.f, 0.f);
            float4 a1 = make_float4(0.f, 0.f, 0.f, 0.f);

            const int beg = g_off[t];
            const int end = g_off[t + 1];

            #pragma unroll 2
            for (int n = beg; n < end; ++n)
                out_step(n, wo, lane, col_idx, d, a0, a1);

            const float inv = 1.0f / d;
            const int c0 = lane * 4;
            smem[(c0 + 0) * 9 + warp] = a0.x * inv;
            smem[(c0 + 1) * 9 + warp] = a0.y * inv;
            smem[(c0 + 2) * 9 + warp] = a0.z * inv;
            smem[(c0 + 3) * 9 + warp] = a0.w * inv;
            smem[(c0 + 128) * 9 + warp] = a1.x * inv;
            smem[(c0 + 129) * 9 + warp] = a1.y * inv;
            smem[(c0 + 130) * 9 + warp] = a1.z * inv;
            smem[(c0 + 131) * 9 + warp] = a1.w * inv;
        }
        __syncthreads();

        const int p  = threadIdx.x & 7;
        const int cb = threadIdx.x >> 3;
        if (pos0 + p < LIGHT_END) {
            #pragma unroll
            for (int j = 0; j < 8; ++j) {
                int c = cb + j * 32;
                out[c * SPX + pos0 + p] = smem[c * 9 + p];
            }
        }
    }
}

// ---------------------------------------------------------------------------
extern "C" void kernel_launch(void* const* d_in, const int* in_sizes, int n_in,
                              void* d_out, int out_size)
{
    const float* qo   = (const float*)d_in[0];
    const float* ki   = (const float*)d_in[1];
    const float* vi   = (const float*)d_in[2];
    const float* q_w  = (const float*)d_in[3];
    const float* k_w  = (const float*)d_in[4];
    const float* v_w  = (const float*)d_in[5];
    const float* q_b  = (const float*)d_in[6];
    const float* k_b  = (const float*)d_in[7];
    const float* v_b  = (const float*)d_in[8];
    const float* quad = (const float*)d_in[9];
    const int* row_ids = (const int*)d_in[10];
    const int* col_idx = (const int*)d_in[11];
    const int nnz = in_sizes[10];

    float* out = (float*)d_out;

    dim3 gg((SPX + 63) / 64, CH / 64, 3);
    proj_kernel<<<gg, 64>>>(qo, ki, vi, q_w, k_w, v_w, q_b, k_b, v_b,
                            row_ids, nnz);

    int score_warps = 3 * nnz;
    score_kernel<<<(score_warps + 7) / 8, 256>>>(row_ids, col_idx, quad, nnz);

    attn_out_kernel<<<HEAVY_BLOCKS + LIGHT_BLOCKS, 256>>>(col_idx, out);
}